// round 12
// baseline (speedup 1.0000x reference)
#include <cuda_runtime.h>
#include <math.h>

#define BB 2
#define CC 5
#define DD 96
#define HH 128
#define WW 128
#define VV (DD*HH*WW)        /* 1572864 */
#define HALFV (VV/2)
#define NW (VV/32)           /* 49152 words per mask */
#define WROW (WW/32)         /* 4 words per row */
#define NMASK 16
#define KSUB 2048
#define NBUCK 4096
#define CANDCAP 8192
#define NPAIR 8              /* B * (C-1) */

/* ---------------- scratch (static device globals; no allocation) -------- */
__device__ unsigned g_rand[VV];          /* threefry word per voxel */
__device__ unsigned g_mask[NMASK][NW];
__device__ unsigned g_bnd[NMASK][NW];
__device__ int      g_hist[NMASK][NBUCK];
__device__ int      g_maskCnt[NMASK];
__device__ int      g_bndTot[NMASK];
__device__ int      g_bStar[NMASK];
__device__ int      g_need[NMASK];
__device__ int      g_sure[NMASK];
__device__ int      g_candCnt[NMASK];
__device__ unsigned g_candKey[NMASK][CANDCAP];
__device__ int      g_candIdx[NMASK][CANDCAP];
__device__ float4   g_pts[NMASK][KSUB];
__device__ double   g_vols[BB][CC];
__device__ double   g_inter[BB][CC-1];
__device__ double   g_psum[BB][CC-1];
__device__ double   g_ce;
__device__ double   g_cham[2][NPAIR];

/* ---------------- threefry2x32-20, JAX semantics, key=(0,42) ------------ */
__device__ __forceinline__ unsigned rotl(unsigned x, int r){ return (x<<r)|(x>>(32-r)); }

__device__ __forceinline__ unsigned threefry_u32(int i){
    unsigned x0, x1;
    if (i < HALFV){ x0 = (unsigned)i;          x1 = (unsigned)(i + HALFV); }
    else          { x0 = (unsigned)(i - HALFV); x1 = (unsigned)i; }
    const unsigned ks0 = 0u, ks1 = 42u, ks2 = 0u ^ 42u ^ 0x1BD11BDAu;
    x0 += ks0; x1 += ks1;
#define TFR(r) { x0 += x1; x1 = rotl(x1,(r)); x1 ^= x0; }
    TFR(13) TFR(15) TFR(26) TFR(6)
    x0 += ks1; x1 += ks2 + 1u;
    TFR(17) TFR(29) TFR(16) TFR(24)
    x0 += ks2; x1 += ks0 + 2u;
    TFR(13) TFR(15) TFR(26) TFR(6)
    x0 += ks0; x1 += ks1 + 3u;
    TFR(17) TFR(29) TFR(16) TFR(24)
    x0 += ks1; x1 += ks2 + 4u;
    TFR(13) TFR(15) TFR(26) TFR(6)
    x0 += ks2; x1 += ks0 + 5u;
#undef TFR
    return (i < HALFV) ? x0 : x1;
}

/* ---------------- kernel 0: zero accumulators + precompute rand table --- */
__global__ void k_init(){
    int i = blockIdx.x*blockDim.x + threadIdx.x;
    int n = gridDim.x*blockDim.x;
    for (int v=i; v<VV; v+=n) g_rand[v] = threefry_u32(v);
    for (int k=i; k<NMASK*NBUCK; k+=n) ((int*)g_hist)[k]=0;
    for (int k=i; k<NMASK*KSUB; k+=n) ((float4*)g_pts)[k]=make_float4(0.f,0.f,0.f,0.f);
    if (i < NMASK){ g_maskCnt[i]=0; g_bndTot[i]=0; g_candCnt[i]=0; g_sure[i]=0; g_bStar[i]=-1; g_need[i]=0; }
    if (i < BB*CC) ((double*)g_vols)[i]=0.0;
    if (i < BB*(CC-1)){ ((double*)g_inter)[i]=0.0; ((double*)g_psum)[i]=0.0; }
    if (i < 2*NPAIR) ((double*)g_cham)[i]=0.0;
    if (i == 0) g_ce = 0.0;
}

/* ---------------- dummy: shifts the ncu capture slot onto k_bnd --------- */
__global__ void k_nop(){}

/* ---------------- kernel 1: fused softmax / stats / bit-packed masks ----
   2 voxels/thread (float2). t[0] never loaded: vol0 derived from one-hot
   (vol0 = blockVoxels - sum vols 1..4) => -10% HBM traffic. All 8 mask
   nibbles packed in ONE u32 (bits: P_m at 2m+j, G_m at 8+2m+j) to cut
   live registers; launch_bounds(256,6) targets 6 blocks/SM.              */
#define KM_G 1024
__global__ void __launch_bounds__(256, 6) k_main(const float* __restrict__ pred,
                                                 const float* __restrict__ tgt){
    int b = blockIdx.y;
    const float2* P2 = (const float2*)(pred + (size_t)b*CC*VV);
    const float2* T2 = (const float2*)(tgt  + (size_t)b*CC*VV);
    int lane = threadIdx.x & 31;
    unsigned grpMask = 0xFFFFu << ((lane>>4)*16);
    bool leader = (lane & 15) == 0;
    int sh = 2*(lane & 15);

    /* acc: 0=ce, 1..4=psum, 5..8=inter, 9..12=vol(c=1..4) — static idx */
    float acc[13];
#pragma unroll
    for (int k=0;k<13;k++) acc[k]=0.f;

#pragma unroll
    for (int it=0; it<3; it++){                 /* VV = 3 * KM_G*512 */
        int v  = it*(KM_G*512) + blockIdx.x*512 + threadIdx.x*2;
        int vi = v >> 1;
        float2 X[CC], T[CC-1];
#pragma unroll
        for (int c=0;c<CC;c++)   X[c] = P2[c*(VV/2) + vi];
#pragma unroll
        for (int c=0;c<CC-1;c++) T[c] = T2[(c+1)*(VV/2) + vi];

        unsigned nib = 0;
#pragma unroll
        for (int j=0;j<2;j++){
            float x[CC], t[CC-1];
#pragma unroll
            for (int c=0;c<CC;c++)   x[c] = j==0 ? X[c].x : X[c].y;
#pragma unroll
            for (int c=0;c<CC-1;c++) t[c] = j==0 ? T[c].x : T[c].y;

            float m = x[0];
#pragma unroll
            for (int c=1;c<CC;c++) m = fmaxf(m, x[c]);
            float e[CC], s = 0.f;
#pragma unroll
            for (int c=0;c<CC;c++){ e[c] = __expf(x[c]-m); s += e[c]; }
            float lse  = m + __logf(s);
            float sinv = __fdividef(1.f, s);
            float p[CC-1];
#pragma unroll
            for (int c=0;c<CC-1;c++) p[c] = e[c+1] * sinv;

            float xlab = x[0];
#pragma unroll
            for (int c=1;c<CC;c++) xlab = (t[c-1] > 0.5f) ? x[c] : xlab;
            acc[0] += lse - xlab;
#pragma unroll
            for (int c=0;c<4;c++){
                acc[1+c] += p[c];
                acc[5+c] += (t[c] > 0.5f) ? p[c] : 0.f;
                acc[9+c] += (t[c] > 0.5f) ? 1.f : 0.f;
            }
#pragma unroll
            for (int c=0;c<4;c++){
                nib |= (p[c] > 0.5f) ? (1u << (2*c     + j)) : 0u;
                nib |= (t[c] > 0.5f) ? (1u << (8 + 2*c + j)) : 0u;
            }
        }
        int wi = v >> 5;                        /* group-uniform word index */
        unsigned w;
#pragma unroll
        for (int c=0;c<4;c++){
            w = __reduce_or_sync(grpMask, (((nib >> (2*c)) & 3u)) << sh);
            if (leader) g_mask[b*4 + c][wi] = w;
        }
#pragma unroll
        for (int c=0;c<4;c++){
            w = __reduce_or_sync(grpMask, (((nib >> (8 + 2*c)) & 3u)) << sh);
            if (leader) g_mask[8 + b*4 + c][wi] = w;
        }
    }

    /* warp tree reduction of 13 floats */
#pragma unroll
    for (int o=16;o;o>>=1)
#pragma unroll
        for (int k=0;k<13;k++) acc[k] += __shfl_down_sync(0xffffffffu, acc[k], o);

    __shared__ float sR[13];
    if (threadIdx.x < 13) sR[threadIdx.x] = 0.f;
    __syncthreads();
    if (lane == 0){
#pragma unroll
        for (int k=0;k<13;k++) atomicAdd(&sR[k], acc[k]);
    }
    __syncthreads();
    if (threadIdx.x == 0){
        atomicAdd(&g_ce, (double)sR[0]);
#pragma unroll
        for (int c=0;c<4;c++){
            atomicAdd(&g_psum[b][c],  (double)sR[1+c]);
            atomicAdd(&g_inter[b][c], (double)sR[5+c]);
            atomicAdd(&g_vols[b][c+1],(double)sR[9+c]);
        }
        float vol0 = 1536.f - sR[9] - sR[10] - sR[11] - sR[12];
        atomicAdd(&g_vols[b][0], (double)vol0);
    }
}

/* ---------------- kernel 2: bit-domain 3x3x3 erosion + score histogram -- */
__global__ void k_bnd(){
    int mIdx = blockIdx.y;
    __shared__ int sh[NBUCK];
    for (int k=threadIdx.x; k<NBUCK; k+=1024) sh[k]=0;
    __syncthreads();

    const unsigned* M = g_mask[mIdx];
    int myCnt = 0;
#pragma unroll
    for (int kk=0; kk<6; kk++){
        int wi = blockIdx.x*6144 + kk*1024 + threadIdx.x;
        int d  = wi / (HH*WROW);
        int r  = wi - d*(HH*WROW);
        int h  = r / WROW;
        int wc = r - h*WROW;
        unsigned center = M[wi];
        unsigned er = 0xFFFFFFFFu;
#pragma unroll
        for (int dz=-1; dz<=1; dz++){
            int dd = d + dz;
            bool okd = (dd>=0 && dd<DD);
#pragma unroll
            for (int dy=-1; dy<=1; dy++){
                int hh = h + dy;
                unsigned tt = 0u;
                if (okd && hh>=0 && hh<HH){
                    int base = (dd*HH + hh)*WROW + wc;
                    unsigned mid = M[base];
                    unsigned lf  = (wc>0)       ? M[base-1] : 0u;
                    unsigned rt  = (wc<WROW-1)  ? M[base+1] : 0u;
                    tt = mid & ((mid<<1)|(lf>>31)) & ((mid>>1)|(rt<<31));
                }
                er &= tt;
            }
        }
        unsigned bnd = center & ~er;
        g_bnd[mIdx][wi] = bnd;
        myCnt += __popc(center);

        unsigned bb = bnd;
        const unsigned* R = g_rand + (wi << 5);
        while (bb){
            int bit = __ffs(bb)-1; bb &= bb-1;
            atomicAdd(&sh[R[bit] >> 20], 1);
        }
    }

#pragma unroll
    for (int o=16;o;o>>=1) myCnt += __shfl_down_sync(0xffffffffu, myCnt, o);
    if ((threadIdx.x & 31)==0 && myCnt) atomicAdd(&g_maskCnt[mIdx], myCnt);

    __syncthreads();
    for (int k=threadIdx.x; k<NBUCK; k+=1024){
        int c = sh[k];
        if (c) atomicAdd(&g_hist[mIdx][k], c);
    }
}

/* ---------------- kernel 3: parallel per-mask threshold bucket ---------- */
__global__ void k_thresh(){
    int m = blockIdx.x;
    int t = threadIdx.x;
    __shared__ int arr[256];

    int h[16];
    int s = 0;
    int base = t*16;
#pragma unroll
    for (int j=0;j<16;j++){ h[j] = g_hist[m][base+j]; s += h[j]; }
    arr[t] = s;
    __syncthreads();

#pragma unroll
    for (int o=1;o<256;o<<=1){
        int add = (t + o < 256) ? arr[t+o] : 0;
        __syncthreads();
        arr[t] += add;
        __syncthreads();
    }

    int tot = arr[0];
    if (t == 0) g_bndTot[m] = tot;
    if (tot <= KSUB) return;

    int cum = arr[t] - s;
#pragma unroll
    for (int j=15;j>=0;j--){
        int c2 = cum + h[j];
        if (cum < KSUB && c2 >= KSUB){
            g_bStar[m] = base + j;
            g_need[m]  = KSUB - cum;
        }
        cum = c2;
    }
}

/* ---------------- kernel 4: collect sure picks + cut-bucket candidates -- */
__global__ void k_select(){
    int m = blockIdx.y;
    int wi = blockIdx.x*blockDim.x + threadIdx.x;
    unsigned bb = g_bnd[m][wi];
    if (!bb) return;
    int bs = g_bStar[m];
    int vbase = wi << 5;
    const unsigned* R = g_rand + vbase;
    while (bb){
        int bit = __ffs(bb)-1; bb &= bb-1;
        unsigned rb = R[bit];
        int bu = (int)(rb >> 20);
        if (bu > bs){
            int v = vbase + bit;
            int pos = atomicAdd(&g_sure[m], 1);
            int dd = v/(HH*WW); int rr = v - dd*HH*WW; int hh = rr/WW; int ww = rr - hh*WW;
            g_pts[m][pos] = make_float4((float)dd,(float)hh,(float)ww,1.f);
        } else if (bu == bs){
            int v = vbase + bit;
            int ci = atomicAdd(&g_candCnt[m], 1);
            if (ci < CANDCAP){ g_candKey[m][ci] = rb >> 9; g_candIdx[m][ci] = v; }
        }
    }
}

/* ---------------- kernel 5: exact rank inside cut bucket ---------------- */
__global__ void k_fincand(){
    int m = blockIdx.x;
    int need = g_need[m];
    if (need <= 0) return;
    int n = min(g_candCnt[m], CANDCAP);
    int base = g_sure[m];
    for (int i=threadIdx.x; i<n; i+=blockDim.x){
        unsigned ki = g_candKey[m][i];
        int ii = g_candIdx[m][i];
        int rank = 0;
        for (int j=0;j<n;j++){
            unsigned kj = g_candKey[m][j];
            if (kj > ki || (kj == ki && g_candIdx[m][j] < ii)) rank++;
        }
        if (rank < need){
            int v = ii;
            int dd = v/(HH*WW); int rr = v - dd*HH*WW; int hh = rr/WW; int ww = rr - hh*WW;
            g_pts[m][base + rank] = make_float4((float)dd,(float)hh,(float)ww,1.f);
        }
    }
}

/* ---------------- kernel 6: chamfer with packed f32x2 fma ----------------
   refs pair-packed in shared: sA={x0,x1,y0,y1}, sB={z0,z1,w0,w1}.
   t = fma(x,qx2, fma(y,qy2, fma(z,qz2, w))) per component — identical
   order/rounding to the scalar version, half the fma-pipe instructions.  */
__global__ void k_cham(){
    int dir  = blockIdx.y;
    int pair = blockIdx.z;
    int mq = dir ? 8 + pair : pair;
    int mr = dir ? pair     : 8 + pair;

    __shared__ float4 sA[KSUB/2];
    __shared__ float4 sB[KSUB/2];
    for (int k=threadIdx.x; k<KSUB/2; k+=blockDim.x){
        float4 r0 = g_pts[mr][2*k];
        float4 r1 = g_pts[mr][2*k+1];
        float w0, w1;
        if (r0.w > 0.5f) w0 = r0.x*r0.x + r0.y*r0.y + r0.z*r0.z;
        else { r0.x=0.f; r0.y=0.f; r0.z=0.f; w0 = 1e30f; }
        if (r1.w > 0.5f) w1 = r1.x*r1.x + r1.y*r1.y + r1.z*r1.z;
        else { r1.x=0.f; r1.y=0.f; r1.z=0.f; w1 = 1e30f; }
        sA[k] = make_float4(r0.x, r1.x, r0.y, r1.y);
        sB[k] = make_float4(r0.z, r1.z, w0, w1);
    }
    __syncthreads();

    int qi = blockIdx.x*blockDim.x + threadIdx.x;
    float4 q = g_pts[mq][qi];
    float contrib = 0.f;
    if (q.w > 0.5f){
        float q2  = q.x*q.x + q.y*q.y + q.z*q.z;
        unsigned qx2u = __float_as_uint(-2.f*q.x);
        unsigned qy2u = __float_as_uint(-2.f*q.y);
        unsigned qz2u = __float_as_uint(-2.f*q.z);
        unsigned long long qx2p, qy2p, qz2p;
        asm("mov.b64 %0, {%1, %1};" : "=l"(qx2p) : "r"(qx2u));
        asm("mov.b64 %0, {%1, %1};" : "=l"(qy2p) : "r"(qy2u));
        asm("mov.b64 %0, {%1, %1};" : "=l"(qz2p) : "r"(qz2u));
        float m0=3.4e38f, m1=3.4e38f, m2=3.4e38f, m3=3.4e38f;
        for (int j=0;j<KSUB/2;j+=2){
            ulonglong2 a0 = *(const ulonglong2*)&sA[j];
            ulonglong2 b0 = *(const ulonglong2*)&sB[j];
            ulonglong2 a1 = *(const ulonglong2*)&sA[j+1];
            ulonglong2 b1 = *(const ulonglong2*)&sB[j+1];
            unsigned long long t0, t1;
            asm("fma.rn.f32x2 %0, %1, %2, %3;" : "=l"(t0) : "l"(b0.x), "l"(qz2p), "l"(b0.y));
            asm("fma.rn.f32x2 %0, %1, %2, %3;" : "=l"(t0) : "l"(a0.y), "l"(qy2p), "l"(t0));
            asm("fma.rn.f32x2 %0, %1, %2, %3;" : "=l"(t0) : "l"(a0.x), "l"(qx2p), "l"(t0));
            asm("fma.rn.f32x2 %0, %1, %2, %3;" : "=l"(t1) : "l"(b1.x), "l"(qz2p), "l"(b1.y));
            asm("fma.rn.f32x2 %0, %1, %2, %3;" : "=l"(t1) : "l"(a1.y), "l"(qy2p), "l"(t1));
            asm("fma.rn.f32x2 %0, %1, %2, %3;" : "=l"(t1) : "l"(a1.x), "l"(qx2p), "l"(t1));
            unsigned lo, hi;
            asm("mov.b64 {%0, %1}, %2;" : "=r"(lo), "=r"(hi) : "l"(t0));
            m0 = fminf(m0, __uint_as_float(lo));
            m1 = fminf(m1, __uint_as_float(hi));
            asm("mov.b64 {%0, %1}, %2;" : "=r"(lo), "=r"(hi) : "l"(t1));
            m2 = fminf(m2, __uint_as_float(lo));
            m3 = fminf(m3, __uint_as_float(hi));
        }
        float tmin = fminf(fminf(m0,m1), fminf(m2,m3));
        contrib = sqrtf(fmaxf(tmin + q2, 0.f));
    }
    __shared__ float sbuf[256];
    sbuf[threadIdx.x] = contrib;
    __syncthreads();
    for (int o=128;o;o>>=1){
        if (threadIdx.x < o) sbuf[threadIdx.x] += sbuf[threadIdx.x + o];
        __syncthreads();
    }
    if (threadIdx.x == 0) atomicAdd(&g_cham[dir][pair], (double)sbuf[0]);
}

/* ---------------- kernel 7: combine everything -------------------------- */
__global__ void k_final(float* out){
    const float SW[5]   = {1.f, 2.f, 1.5f, 2.5f, 1.5f};
    const float BASE[5] = {0.f, 2000.f, 8000.f, 1000.f, 3000.f};

    float dw[BB][CC];
    for (int b=0;b<BB;b++){
        float eff[CC], mx = 0.f;
        for (int c=0;c<CC;c++){
            float vv = (float)g_vols[b][c];
            float mult = fminf(sqrtf(BASE[c] / fmaxf(vv, 1e-5f)), 2.5f);
            eff[c] = SW[c]*mult;
            mx = fmaxf(mx, eff[c]);
        }
        for (int c=0;c<CC;c++) dw[b][c] = eff[c] / fmaxf(mx, 1e-5f);
    }

    double diceSum = 0.0, tvSum = 0.0;
    for (int b=0;b<BB;b++)
        for (int c=0;c<4;c++){
            double I = g_inter[b][c], P = g_psum[b][c], G = g_vols[b][c+1];
            diceSum += 1.0 - (2.0*I + 1e-5) / (P + G + 1e-5);
            double fp = P - I, fn = G - I;
            tvSum   += 1.0 - (I + 1e-5) / (I + 0.3*fp + 0.7*fn + 1e-5);
        }
    double ce = g_ce / ((double)BB * (double)VV);
    double dice_ce = 0.5*(diceSum/8.0) + 0.5*ce;

    double ssum = 0.0;
    for (int b=0;b<BB;b++){
        double cs = 0.0; int nval = 0;
        for (int c=0;c<4;c++){
            int pc = g_maskCnt[b*4 + c];
            int gc = g_maskCnt[8 + b*4 + c];
            bool p0 = (pc==0), g0 = (gc==0);
            if (p0 && g0) continue;
            nval++;
            double w = (double)dw[b][c+1];
            if (p0 != g0){ cs += w*10.0; }
            else {
                int pair = b*4 + c;
                int np = min(g_bndTot[pair],     KSUB); if (np < 1) np = 1;
                int nt = min(g_bndTot[8 + pair], KSUB); if (nt < 1) nt = 1;
                double mp = g_cham[0][pair] / (double)np;
                double mt = g_cham[1][pair] / (double)nt;
                cs += w * 0.5 * (mp + mt);
            }
        }
        ssum += (nval > 0) ? cs / (double)nval : 0.0;
    }
    double total = 0.4*dice_ce + 0.4*(tvSum/8.0) + 0.2*(ssum/(double)BB);
    out[0] = (float)total;
}

/* ---------------- launch ------------------------------------------------ */
extern "C" void kernel_launch(void* const* d_in, const int* in_sizes, int n_in,
                              void* d_out, int out_size){
    const float* pred = (const float*)d_in[0];
    const float* tgt  = (const float*)d_in[1];
    float* out = (float*)d_out;

    k_init<<<1024, 256>>>();
    k_nop<<<1, 32>>>();                      /* ncu window (4th) -> k_bnd */
    k_main<<<dim3(KM_G, BB), 256>>>(pred, tgt);
    k_bnd<<<dim3(8, NMASK), 1024>>>();
    k_thresh<<<NMASK, 256>>>();
    dim3 gs(NW/256, NMASK);
    k_select<<<gs, 256>>>();
    k_fincand<<<NMASK, 256>>>();
    k_cham<<<dim3(KSUB/256, 2, NPAIR), 256>>>();
    k_final<<<1, 1>>>(out);
}

// round 14
// speedup vs baseline: 1.0686x; 1.0686x over previous
#include <cuda_runtime.h>
#include <math.h>

#define BB 2
#define CC 5
#define DD 96
#define HH 128
#define WW 128
#define VV (DD*HH*WW)        /* 1572864 */
#define HALFV (VV/2)
#define NW (VV/32)           /* 49152 words per mask */
#define WROW (WW/32)         /* 4 words per row */
#define NMASK 16
#define KSUB 2048
#define NBUCK 4096
#define CANDCAP 8192
#define NPAIR 8              /* B * (C-1) */

/* ---------------- scratch (static device globals; no allocation) -------- */
__device__ unsigned g_rand[VV];          /* threefry word per voxel */
__device__ unsigned g_mask[NMASK][NW];
__device__ unsigned g_bnd[NMASK][NW];
__device__ int      g_hist[NMASK][NBUCK];
__device__ int      g_maskCnt[NMASK];
__device__ int      g_bndTot[NMASK];
__device__ int      g_bStar[NMASK];
__device__ int      g_need[NMASK];
__device__ int      g_sure[NMASK];
__device__ int      g_candCnt[NMASK];
__device__ unsigned g_candKey[NMASK][CANDCAP];
__device__ int      g_candIdx[NMASK][CANDCAP];
__device__ float4   g_pts[NMASK][KSUB];
__device__ double   g_vols[BB][CC];
__device__ double   g_inter[BB][CC-1];
__device__ double   g_psum[BB][CC-1];
__device__ double   g_ce;
__device__ double   g_cham[2][NPAIR];

/* ---------------- threefry2x32-20, JAX semantics, key=(0,42) ------------ */
__device__ __forceinline__ unsigned rotl(unsigned x, int r){ return (x<<r)|(x>>(32-r)); }

__device__ __forceinline__ unsigned threefry_u32(int i){
    unsigned x0, x1;
    if (i < HALFV){ x0 = (unsigned)i;          x1 = (unsigned)(i + HALFV); }
    else          { x0 = (unsigned)(i - HALFV); x1 = (unsigned)i; }
    const unsigned ks0 = 0u, ks1 = 42u, ks2 = 0u ^ 42u ^ 0x1BD11BDAu;
    x0 += ks0; x1 += ks1;
#define TFR(r) { x0 += x1; x1 = rotl(x1,(r)); x1 ^= x0; }
    TFR(13) TFR(15) TFR(26) TFR(6)
    x0 += ks1; x1 += ks2 + 1u;
    TFR(17) TFR(29) TFR(16) TFR(24)
    x0 += ks2; x1 += ks0 + 2u;
    TFR(13) TFR(15) TFR(26) TFR(6)
    x0 += ks0; x1 += ks1 + 3u;
    TFR(17) TFR(29) TFR(16) TFR(24)
    x0 += ks1; x1 += ks2 + 4u;
    TFR(13) TFR(15) TFR(26) TFR(6)
    x0 += ks2; x1 += ks0 + 5u;
#undef TFR
    return (i < HALFV) ? x0 : x1;
}

/* ---------------- kernel 0: zero accumulators + precompute rand table --- */
__global__ void k_init(){
    int i = blockIdx.x*blockDim.x + threadIdx.x;
    int n = gridDim.x*blockDim.x;
    for (int v=i; v<VV; v+=n) g_rand[v] = threefry_u32(v);
    for (int k=i; k<NMASK*NBUCK; k+=n) ((int*)g_hist)[k]=0;
    for (int k=i; k<NMASK*KSUB; k+=n) ((float4*)g_pts)[k]=make_float4(0.f,0.f,0.f,0.f);
    if (i < NMASK){ g_maskCnt[i]=0; g_bndTot[i]=0; g_candCnt[i]=0; g_sure[i]=0; g_bStar[i]=-1; g_need[i]=0; }
    if (i < BB*CC) ((double*)g_vols)[i]=0.0;
    if (i < BB*(CC-1)){ ((double*)g_inter)[i]=0.0; ((double*)g_psum)[i]=0.0; }
    if (i < 2*NPAIR) ((double*)g_cham)[i]=0.0;
    if (i == 0) g_ce = 0.0;
}

/* ---------------- dummy: shifts the ncu capture slot onto k_bnd --------- */
__global__ void k_nop(){}

/* ---------------- kernel 1: fused softmax / stats / bit-packed masks ----
   R11 version (measured 44.2us): 2 voxels/thread float2, launch_bounds
   (256,5), 16-lane-group __reduce_or_sync mask packing.                  */
#define KM_G 1024
__global__ void __launch_bounds__(256, 5) k_main(const float* __restrict__ pred,
                                                 const float* __restrict__ tgt){
    int b = blockIdx.y;
    const float2* P2 = (const float2*)(pred + (size_t)b*CC*VV);
    const float2* T2 = (const float2*)(tgt  + (size_t)b*CC*VV);
    int lane = threadIdx.x & 31;
    unsigned grpMask = 0xFFFFu << ((lane>>4)*16);
    bool leader = (lane & 15) == 0;
    int sh = 2*(lane & 15);

    float acc[14];
#pragma unroll
    for (int k=0;k<14;k++) acc[k]=0.f;

#pragma unroll
    for (int it=0; it<3; it++){                 /* VV = 3 * KM_G*512 */
        int v  = it*(KM_G*512) + blockIdx.x*512 + threadIdx.x*2;
        int vi = v >> 1;
        float2 X[CC], T[CC];
#pragma unroll
        for (int c=0;c<CC;c++){
            X[c] = P2[c*(VV/2) + vi];
            T[c] = T2[c*(VV/2) + vi];
        }
        unsigned nibP0=0,nibP1=0,nibP2=0,nibP3=0;
        unsigned nibG0=0,nibG1=0,nibG2=0,nibG3=0;
#pragma unroll
        for (int j=0;j<2;j++){
            float x[CC], t[CC];
#pragma unroll
            for (int c=0;c<CC;c++){
                x[c] = j==0 ? X[c].x : X[c].y;
                t[c] = j==0 ? T[c].x : T[c].y;
            }
            float m = x[0];
#pragma unroll
            for (int c=1;c<CC;c++) m = fmaxf(m, x[c]);
            float e[CC], s = 0.f;
#pragma unroll
            for (int c=0;c<CC;c++){ e[c] = __expf(x[c]-m); s += e[c]; }
            float lse  = m + __logf(s);
            float sinv = __fdividef(1.f, s);
            float p[CC-1];
#pragma unroll
            for (int c=0;c<CC-1;c++) p[c] = e[c+1] * sinv;

            float xlab = x[0];
#pragma unroll
            for (int c=1;c<CC;c++) xlab = (t[c] > 0.5f) ? x[c] : xlab;
            acc[0] += lse - xlab;
#pragma unroll
            for (int c=0;c<4;c++){
                acc[1+c] += p[c];
                acc[5+c] += (t[c+1] > 0.5f) ? p[c] : 0.f;
            }
#pragma unroll
            for (int c=0;c<CC;c++) acc[9+c] += (t[c] > 0.5f) ? 1.f : 0.f;

            nibP0 |= (p[0] > 0.5f) ? (1u<<j) : 0u;
            nibP1 |= (p[1] > 0.5f) ? (1u<<j) : 0u;
            nibP2 |= (p[2] > 0.5f) ? (1u<<j) : 0u;
            nibP3 |= (p[3] > 0.5f) ? (1u<<j) : 0u;
            nibG0 |= (t[1] > 0.5f) ? (1u<<j) : 0u;
            nibG1 |= (t[2] > 0.5f) ? (1u<<j) : 0u;
            nibG2 |= (t[3] > 0.5f) ? (1u<<j) : 0u;
            nibG3 |= (t[4] > 0.5f) ? (1u<<j) : 0u;
        }
        int wi = v >> 5;
        unsigned w;
        w = __reduce_or_sync(grpMask, nibP0 << sh); if (leader) g_mask[b*4+0][wi] = w;
        w = __reduce_or_sync(grpMask, nibP1 << sh); if (leader) g_mask[b*4+1][wi] = w;
        w = __reduce_or_sync(grpMask, nibP2 << sh); if (leader) g_mask[b*4+2][wi] = w;
        w = __reduce_or_sync(grpMask, nibP3 << sh); if (leader) g_mask[b*4+3][wi] = w;
        w = __reduce_or_sync(grpMask, nibG0 << sh); if (leader) g_mask[8+b*4+0][wi] = w;
        w = __reduce_or_sync(grpMask, nibG1 << sh); if (leader) g_mask[8+b*4+1][wi] = w;
        w = __reduce_or_sync(grpMask, nibG2 << sh); if (leader) g_mask[8+b*4+2][wi] = w;
        w = __reduce_or_sync(grpMask, nibG3 << sh); if (leader) g_mask[8+b*4+3][wi] = w;
    }

#pragma unroll
    for (int o=16;o;o>>=1)
#pragma unroll
        for (int k=0;k<14;k++) acc[k] += __shfl_down_sync(0xffffffffu, acc[k], o);

    __shared__ float sR[14];
    if (threadIdx.x < 14) sR[threadIdx.x] = 0.f;
    __syncthreads();
    if (lane == 0){
#pragma unroll
        for (int k=0;k<14;k++) atomicAdd(&sR[k], acc[k]);
    }
    __syncthreads();
    if (threadIdx.x == 0){
        atomicAdd(&g_ce, (double)sR[0]);
#pragma unroll
        for (int c=0;c<4;c++){
            atomicAdd(&g_psum[b][c],  (double)sR[1+c]);
            atomicAdd(&g_inter[b][c], (double)sR[5+c]);
        }
#pragma unroll
        for (int c=0;c<CC;c++) atomicAdd(&g_vols[b][c], (double)sR[9+c]);
    }
}

/* ---------------- kernel 2: bit-domain 3x3x3 erosion + score histogram --
   256 blocks (16 per mask) x 1024 threads, 3 words/thread: ~2 blocks/SM
   => up to 64 warps/SM to cover the serialized per-bit loop latency.     */
__global__ void k_bnd(){
    int mIdx = blockIdx.y;
    __shared__ int sh[NBUCK];
    for (int k=threadIdx.x; k<NBUCK; k+=1024) sh[k]=0;
    __syncthreads();

    const unsigned* M = g_mask[mIdx];
    int myCnt = 0;
#pragma unroll
    for (int kk=0; kk<3; kk++){
        int wi = blockIdx.x*3072 + kk*1024 + threadIdx.x;
        int d  = wi / (HH*WROW);
        int r  = wi - d*(HH*WROW);
        int h  = r / WROW;
        int wc = r - h*WROW;
        unsigned center = M[wi];
        unsigned er = 0xFFFFFFFFu;
#pragma unroll
        for (int dz=-1; dz<=1; dz++){
            int dd = d + dz;
            bool okd = (dd>=0 && dd<DD);
#pragma unroll
            for (int dy=-1; dy<=1; dy++){
                int hh = h + dy;
                unsigned tt = 0u;
                if (okd && hh>=0 && hh<HH){
                    int base = (dd*HH + hh)*WROW + wc;
                    unsigned mid = M[base];
                    unsigned lf  = (wc>0)       ? M[base-1] : 0u;
                    unsigned rt  = (wc<WROW-1)  ? M[base+1] : 0u;
                    tt = mid & ((mid<<1)|(lf>>31)) & ((mid>>1)|(rt<<31));
                }
                er &= tt;
            }
        }
        unsigned bnd = center & ~er;
        g_bnd[mIdx][wi] = bnd;
        myCnt += __popc(center);

        unsigned bb = bnd;
        const unsigned* R = g_rand + (wi << 5);
        while (bb){
            int bit = __ffs(bb)-1; bb &= bb-1;
            atomicAdd(&sh[R[bit] >> 20], 1);
        }
    }

#pragma unroll
    for (int o=16;o;o>>=1) myCnt += __shfl_down_sync(0xffffffffu, myCnt, o);
    if ((threadIdx.x & 31)==0 && myCnt) atomicAdd(&g_maskCnt[mIdx], myCnt);

    __syncthreads();
    for (int k=threadIdx.x; k<NBUCK; k+=1024){
        int c = sh[k];
        if (c) atomicAdd(&g_hist[mIdx][k], c);
    }
}

/* ---------------- kernel 3: parallel per-mask threshold bucket ---------- */
__global__ void k_thresh(){
    int m = blockIdx.x;
    int t = threadIdx.x;
    __shared__ int arr[256];

    int h[16];
    int s = 0;
    int base = t*16;
#pragma unroll
    for (int j=0;j<16;j++){ h[j] = g_hist[m][base+j]; s += h[j]; }
    arr[t] = s;
    __syncthreads();

#pragma unroll
    for (int o=1;o<256;o<<=1){
        int add = (t + o < 256) ? arr[t+o] : 0;
        __syncthreads();
        arr[t] += add;
        __syncthreads();
    }

    int tot = arr[0];
    if (t == 0) g_bndTot[m] = tot;
    if (tot <= KSUB) return;

    int cum = arr[t] - s;
#pragma unroll
    for (int j=15;j>=0;j--){
        int c2 = cum + h[j];
        if (cum < KSUB && c2 >= KSUB){
            g_bStar[m] = base + j;
            g_need[m]  = KSUB - cum;
        }
        cum = c2;
    }
}

/* ---------------- kernel 4: collect sure picks + cut-bucket candidates -- */
__global__ void k_select(){
    int m = blockIdx.y;
    int wi = blockIdx.x*blockDim.x + threadIdx.x;
    unsigned bb = g_bnd[m][wi];
    if (!bb) return;
    int bs = g_bStar[m];
    int vbase = wi << 5;
    const unsigned* R = g_rand + vbase;
    while (bb){
        int bit = __ffs(bb)-1; bb &= bb-1;
        unsigned rb = R[bit];
        int bu = (int)(rb >> 20);
        if (bu > bs){
            int v = vbase + bit;
            int pos = atomicAdd(&g_sure[m], 1);
            int dd = v/(HH*WW); int rr = v - dd*HH*WW; int hh = rr/WW; int ww = rr - hh*WW;
            g_pts[m][pos] = make_float4((float)dd,(float)hh,(float)ww,1.f);
        } else if (bu == bs){
            int v = vbase + bit;
            int ci = atomicAdd(&g_candCnt[m], 1);
            if (ci < CANDCAP){ g_candKey[m][ci] = rb >> 9; g_candIdx[m][ci] = v; }
        }
    }
}

/* ---------------- kernel 5: exact rank inside cut bucket ---------------- */
__global__ void k_fincand(){
    int m = blockIdx.x;
    int need = g_need[m];
    if (need <= 0) return;
    int n = min(g_candCnt[m], CANDCAP);
    int base = g_sure[m];
    for (int i=threadIdx.x; i<n; i+=blockDim.x){
        unsigned ki = g_candKey[m][i];
        int ii = g_candIdx[m][i];
        int rank = 0;
        for (int j=0;j<n;j++){
            unsigned kj = g_candKey[m][j];
            if (kj > ki || (kj == ki && g_candIdx[m][j] < ii)) rank++;
        }
        if (rank < need){
            int v = ii;
            int dd = v/(HH*WW); int rr = v - dd*HH*WW; int hh = rr/WW; int ww = rr - hh*WW;
            g_pts[m][base + rank] = make_float4((float)dd,(float)hh,(float)ww,1.f);
        }
    }
}

/* ---------------- kernel 6: chamfer (R11 scalar fmaf version) ----------- */
__global__ void k_cham(){
    int dir  = blockIdx.y;
    int pair = blockIdx.z;
    int mq = dir ? 8 + pair : pair;
    int mr = dir ? pair     : 8 + pair;

    __shared__ float4 sref[KSUB];
    for (int k=threadIdx.x; k<KSUB; k+=blockDim.x){
        float4 rr = g_pts[mr][k];
        if (rr.w > 0.5f) rr.w = rr.x*rr.x + rr.y*rr.y + rr.z*rr.z;
        else { rr.x=0.f; rr.y=0.f; rr.z=0.f; rr.w=1e30f; }
        sref[k] = rr;
    }
    __syncthreads();

    int qi = blockIdx.x*blockDim.x + threadIdx.x;
    float4 q = g_pts[mq][qi];
    float contrib = 0.f;
    if (q.w > 0.5f){
        float q2  = q.x*q.x + q.y*q.y + q.z*q.z;
        float qx2 = -2.f*q.x, qy2 = -2.f*q.y, qz2 = -2.f*q.z;
        float m0=3.4e38f, m1=3.4e38f, m2=3.4e38f, m3=3.4e38f;
        for (int j=0;j<KSUB;j+=4){
            float4 r0=sref[j], r1=sref[j+1], r2=sref[j+2], r3=sref[j+3];
            float t0 = fmaf(r0.x, qx2, fmaf(r0.y, qy2, fmaf(r0.z, qz2, r0.w)));
            float t1 = fmaf(r1.x, qx2, fmaf(r1.y, qy2, fmaf(r1.z, qz2, r1.w)));
            float t2 = fmaf(r2.x, qx2, fmaf(r2.y, qy2, fmaf(r2.z, qz2, r2.w)));
            float t3 = fmaf(r3.x, qx2, fmaf(r3.y, qy2, fmaf(r3.z, qz2, r3.w)));
            m0 = fminf(m0,t0); m1 = fminf(m1,t1);
            m2 = fminf(m2,t2); m3 = fminf(m3,t3);
        }
        float tmin = fminf(fminf(m0,m1), fminf(m2,m3));
        contrib = sqrtf(fmaxf(tmin + q2, 0.f));
    }
    __shared__ float sbuf[256];
    sbuf[threadIdx.x] = contrib;
    __syncthreads();
    for (int o=128;o;o>>=1){
        if (threadIdx.x < o) sbuf[threadIdx.x] += sbuf[threadIdx.x + o];
        __syncthreads();
    }
    if (threadIdx.x == 0) atomicAdd(&g_cham[dir][pair], (double)sbuf[0]);
}

/* ---------------- kernel 7: combine everything -------------------------- */
__global__ void k_final(float* out){
    const float SW[5]   = {1.f, 2.f, 1.5f, 2.5f, 1.5f};
    const float BASE[5] = {0.f, 2000.f, 8000.f, 1000.f, 3000.f};

    float dw[BB][CC];
    for (int b=0;b<BB;b++){
        float eff[CC], mx = 0.f;
        for (int c=0;c<CC;c++){
            float vv = (float)g_vols[b][c];
            float mult = fminf(sqrtf(BASE[c] / fmaxf(vv, 1e-5f)), 2.5f);
            eff[c] = SW[c]*mult;
            mx = fmaxf(mx, eff[c]);
        }
        for (int c=0;c<CC;c++) dw[b][c] = eff[c] / fmaxf(mx, 1e-5f);
    }

    double diceSum = 0.0, tvSum = 0.0;
    for (int b=0;b<BB;b++)
        for (int c=0;c<4;c++){
            double I = g_inter[b][c], P = g_psum[b][c], G = g_vols[b][c+1];
            diceSum += 1.0 - (2.0*I + 1e-5) / (P + G + 1e-5);
            double fp = P - I, fn = G - I;
            tvSum   += 1.0 - (I + 1e-5) / (I + 0.3*fp + 0.7*fn + 1e-5);
        }
    double ce = g_ce / ((double)BB * (double)VV);
    double dice_ce = 0.5*(diceSum/8.0) + 0.5*ce;

    double ssum = 0.0;
    for (int b=0;b<BB;b++){
        double cs = 0.0; int nval = 0;
        for (int c=0;c<4;c++){
            int pc = g_maskCnt[b*4 + c];
            int gc = g_maskCnt[8 + b*4 + c];
            bool p0 = (pc==0), g0 = (gc==0);
            if (p0 && g0) continue;
            nval++;
            double w = (double)dw[b][c+1];
            if (p0 != g0){ cs += w*10.0; }
            else {
                int pair = b*4 + c;
                int np = min(g_bndTot[pair],     KSUB); if (np < 1) np = 1;
                int nt = min(g_bndTot[8 + pair], KSUB); if (nt < 1) nt = 1;
                double mp = g_cham[0][pair] / (double)np;
                double mt = g_cham[1][pair] / (double)nt;
                cs += w * 0.5 * (mp + mt);
            }
        }
        ssum += (nval > 0) ? cs / (double)nval : 0.0;
    }
    double total = 0.4*dice_ce + 0.4*(tvSum/8.0) + 0.2*(ssum/(double)BB);
    out[0] = (float)total;
}

/* ---------------- launch ------------------------------------------------ */
extern "C" void kernel_launch(void* const* d_in, const int* in_sizes, int n_in,
                              void* d_out, int out_size){
    const float* pred = (const float*)d_in[0];
    const float* tgt  = (const float*)d_in[1];
    float* out = (float*)d_out;

    k_init<<<1024, 256>>>();
    k_nop<<<1, 32>>>();                      /* ncu window (4th) -> k_bnd */
    k_main<<<dim3(KM_G, BB), 256>>>(pred, tgt);
    k_bnd<<<dim3(16, NMASK), 1024>>>();
    k_thresh<<<NMASK, 256>>>();
    dim3 gs(NW/256, NMASK);
    k_select<<<gs, 256>>>();
    k_fincand<<<NMASK, 256>>>();
    k_cham<<<dim3(KSUB/256, 2, NPAIR), 256>>>();
    k_final<<<1, 1>>>(out);
}

// round 15
// speedup vs baseline: 1.0758x; 1.0067x over previous
#include <cuda_runtime.h>
#include <math.h>

#define BB 2
#define CC 5
#define DD 96
#define HH 128
#define WW 128
#define VV (DD*HH*WW)        /* 1572864 */
#define HALFV (VV/2)
#define NW (VV/32)           /* 49152 words per mask */
#define WROW (WW/32)         /* 4 words per row */
#define NMASK 16
#define KSUB 2048
#define NBUCK 4096
#define CANDCAP 8192
#define NPAIR 8              /* B * (C-1) */

/* ---------------- scratch (static device globals; no allocation) -------- */
__device__ unsigned g_rand[VV];          /* threefry word per voxel */
__device__ unsigned g_mask[NMASK][NW];
__device__ unsigned g_bnd[NMASK][NW];
__device__ int      g_hist[NMASK][NBUCK];
__device__ int      g_bndDone[NMASK];
__device__ int      g_maskCnt[NMASK];
__device__ int      g_bndTot[NMASK];
__device__ int      g_bStar[NMASK];
__device__ int      g_need[NMASK];
__device__ int      g_sure[NMASK];
__device__ int      g_candCnt[NMASK];
__device__ unsigned g_candKey[NMASK][CANDCAP];
__device__ int      g_candIdx[NMASK][CANDCAP];
__device__ float4   g_pts[NMASK][KSUB];
__device__ double   g_vols[BB][CC];
__device__ double   g_inter[BB][CC-1];
__device__ double   g_psum[BB][CC-1];
__device__ double   g_ce;
__device__ double   g_cham[2][NPAIR];

/* ---------------- threefry2x32-20, JAX semantics, key=(0,42) ------------ */
__device__ __forceinline__ unsigned rotl(unsigned x, int r){ return (x<<r)|(x>>(32-r)); }

__device__ __forceinline__ unsigned threefry_u32(int i){
    unsigned x0, x1;
    if (i < HALFV){ x0 = (unsigned)i;          x1 = (unsigned)(i + HALFV); }
    else          { x0 = (unsigned)(i - HALFV); x1 = (unsigned)i; }
    const unsigned ks0 = 0u, ks1 = 42u, ks2 = 0u ^ 42u ^ 0x1BD11BDAu;
    x0 += ks0; x1 += ks1;
#define TFR(r) { x0 += x1; x1 = rotl(x1,(r)); x1 ^= x0; }
    TFR(13) TFR(15) TFR(26) TFR(6)
    x0 += ks1; x1 += ks2 + 1u;
    TFR(17) TFR(29) TFR(16) TFR(24)
    x0 += ks2; x1 += ks0 + 2u;
    TFR(13) TFR(15) TFR(26) TFR(6)
    x0 += ks0; x1 += ks1 + 3u;
    TFR(17) TFR(29) TFR(16) TFR(24)
    x0 += ks1; x1 += ks2 + 4u;
    TFR(13) TFR(15) TFR(26) TFR(6)
    x0 += ks2; x1 += ks0 + 5u;
#undef TFR
    return (i < HALFV) ? x0 : x1;
}

/* ---------------- kernel 0: zero accumulators + precompute rand table --- */
__global__ void k_init(){
    int i = blockIdx.x*blockDim.x + threadIdx.x;
    int n = gridDim.x*blockDim.x;
    for (int v=i; v<VV; v+=n) g_rand[v] = threefry_u32(v);
    for (int k=i; k<NMASK*NBUCK; k+=n) ((int*)g_hist)[k]=0;
    for (int k=i; k<NMASK*KSUB; k+=n) ((float4*)g_pts)[k]=make_float4(0.f,0.f,0.f,0.f);
    if (i < NMASK){ g_maskCnt[i]=0; g_bndTot[i]=0; g_candCnt[i]=0; g_sure[i]=0; g_bStar[i]=-1; g_need[i]=0; g_bndDone[i]=0; }
    if (i < BB*CC) ((double*)g_vols)[i]=0.0;
    if (i < BB*(CC-1)){ ((double*)g_inter)[i]=0.0; ((double*)g_psum)[i]=0.0; }
    if (i < 2*NPAIR) ((double*)g_cham)[i]=0.0;
    if (i == 0) g_ce = 0.0;
}

/* ---------------- kernel 1: fused softmax / stats / bit-packed masks ----
   R11 version (measured 44.2us).                                         */
#define KM_G 1024
__global__ void __launch_bounds__(256, 5) k_main(const float* __restrict__ pred,
                                                 const float* __restrict__ tgt){
    int b = blockIdx.y;
    const float2* P2 = (const float2*)(pred + (size_t)b*CC*VV);
    const float2* T2 = (const float2*)(tgt  + (size_t)b*CC*VV);
    int lane = threadIdx.x & 31;
    unsigned grpMask = 0xFFFFu << ((lane>>4)*16);
    bool leader = (lane & 15) == 0;
    int sh = 2*(lane & 15);

    float acc[14];
#pragma unroll
    for (int k=0;k<14;k++) acc[k]=0.f;

#pragma unroll
    for (int it=0; it<3; it++){                 /* VV = 3 * KM_G*512 */
        int v  = it*(KM_G*512) + blockIdx.x*512 + threadIdx.x*2;
        int vi = v >> 1;
        float2 X[CC], T[CC];
#pragma unroll
        for (int c=0;c<CC;c++){
            X[c] = P2[c*(VV/2) + vi];
            T[c] = T2[c*(VV/2) + vi];
        }
        unsigned nibP0=0,nibP1=0,nibP2=0,nibP3=0;
        unsigned nibG0=0,nibG1=0,nibG2=0,nibG3=0;
#pragma unroll
        for (int j=0;j<2;j++){
            float x[CC], t[CC];
#pragma unroll
            for (int c=0;c<CC;c++){
                x[c] = j==0 ? X[c].x : X[c].y;
                t[c] = j==0 ? T[c].x : T[c].y;
            }
            float m = x[0];
#pragma unroll
            for (int c=1;c<CC;c++) m = fmaxf(m, x[c]);
            float e[CC], s = 0.f;
#pragma unroll
            for (int c=0;c<CC;c++){ e[c] = __expf(x[c]-m); s += e[c]; }
            float lse  = m + __logf(s);
            float sinv = __fdividef(1.f, s);
            float p[CC-1];
#pragma unroll
            for (int c=0;c<CC-1;c++) p[c] = e[c+1] * sinv;

            float xlab = x[0];
#pragma unroll
            for (int c=1;c<CC;c++) xlab = (t[c] > 0.5f) ? x[c] : xlab;
            acc[0] += lse - xlab;
#pragma unroll
            for (int c=0;c<4;c++){
                acc[1+c] += p[c];
                acc[5+c] += (t[c+1] > 0.5f) ? p[c] : 0.f;
            }
#pragma unroll
            for (int c=0;c<CC;c++) acc[9+c] += (t[c] > 0.5f) ? 1.f : 0.f;

            nibP0 |= (p[0] > 0.5f) ? (1u<<j) : 0u;
            nibP1 |= (p[1] > 0.5f) ? (1u<<j) : 0u;
            nibP2 |= (p[2] > 0.5f) ? (1u<<j) : 0u;
            nibP3 |= (p[3] > 0.5f) ? (1u<<j) : 0u;
            nibG0 |= (t[1] > 0.5f) ? (1u<<j) : 0u;
            nibG1 |= (t[2] > 0.5f) ? (1u<<j) : 0u;
            nibG2 |= (t[3] > 0.5f) ? (1u<<j) : 0u;
            nibG3 |= (t[4] > 0.5f) ? (1u<<j) : 0u;
        }
        int wi = v >> 5;
        unsigned w;
        w = __reduce_or_sync(grpMask, nibP0 << sh); if (leader) g_mask[b*4+0][wi] = w;
        w = __reduce_or_sync(grpMask, nibP1 << sh); if (leader) g_mask[b*4+1][wi] = w;
        w = __reduce_or_sync(grpMask, nibP2 << sh); if (leader) g_mask[b*4+2][wi] = w;
        w = __reduce_or_sync(grpMask, nibP3 << sh); if (leader) g_mask[b*4+3][wi] = w;
        w = __reduce_or_sync(grpMask, nibG0 << sh); if (leader) g_mask[8+b*4+0][wi] = w;
        w = __reduce_or_sync(grpMask, nibG1 << sh); if (leader) g_mask[8+b*4+1][wi] = w;
        w = __reduce_or_sync(grpMask, nibG2 << sh); if (leader) g_mask[8+b*4+2][wi] = w;
        w = __reduce_or_sync(grpMask, nibG3 << sh); if (leader) g_mask[8+b*4+3][wi] = w;
    }

#pragma unroll
    for (int o=16;o;o>>=1)
#pragma unroll
        for (int k=0;k<14;k++) acc[k] += __shfl_down_sync(0xffffffffu, acc[k], o);

    __shared__ float sR[14];
    if (threadIdx.x < 14) sR[threadIdx.x] = 0.f;
    __syncthreads();
    if (lane == 0){
#pragma unroll
        for (int k=0;k<14;k++) atomicAdd(&sR[k], acc[k]);
    }
    __syncthreads();
    if (threadIdx.x == 0){
        atomicAdd(&g_ce, (double)sR[0]);
#pragma unroll
        for (int c=0;c<4;c++){
            atomicAdd(&g_psum[b][c],  (double)sR[1+c]);
            atomicAdd(&g_inter[b][c], (double)sR[5+c]);
        }
#pragma unroll
        for (int c=0;c<CC;c++) atomicAdd(&g_vols[b][c], (double)sR[9+c]);
    }
}

/* ---------------- kernel 2: erosion + histogram + FUSED threshold --------
   256 blocks (16 per mask) x 1024 threads. The LAST finishing block of
   each mask (ticket counter + threadfence) runs the threshold suffix
   scan that used to be kernel k_thresh.                                  */
__global__ void k_bnd(){
    int mIdx = blockIdx.y;
    __shared__ int sh[NBUCK];
    for (int k=threadIdx.x; k<NBUCK; k+=1024) sh[k]=0;
    __syncthreads();

    const unsigned* M = g_mask[mIdx];
    int myCnt = 0;
#pragma unroll
    for (int kk=0; kk<3; kk++){
        int wi = blockIdx.x*3072 + kk*1024 + threadIdx.x;
        int d  = wi / (HH*WROW);
        int r  = wi - d*(HH*WROW);
        int h  = r / WROW;
        int wc = r - h*WROW;
        unsigned center = M[wi];
        unsigned er = 0xFFFFFFFFu;
#pragma unroll
        for (int dz=-1; dz<=1; dz++){
            int dd = d + dz;
            bool okd = (dd>=0 && dd<DD);
#pragma unroll
            for (int dy=-1; dy<=1; dy++){
                int hh = h + dy;
                unsigned tt = 0u;
                if (okd && hh>=0 && hh<HH){
                    int base = (dd*HH + hh)*WROW + wc;
                    unsigned mid = M[base];
                    unsigned lf  = (wc>0)       ? M[base-1] : 0u;
                    unsigned rt  = (wc<WROW-1)  ? M[base+1] : 0u;
                    tt = mid & ((mid<<1)|(lf>>31)) & ((mid>>1)|(rt<<31));
                }
                er &= tt;
            }
        }
        unsigned bnd = center & ~er;
        g_bnd[mIdx][wi] = bnd;
        myCnt += __popc(center);

        unsigned bb = bnd;
        const unsigned* R = g_rand + (wi << 5);
        while (bb){
            int bit = __ffs(bb)-1; bb &= bb-1;
            atomicAdd(&sh[R[bit] >> 20], 1);
        }
    }

#pragma unroll
    for (int o=16;o;o>>=1) myCnt += __shfl_down_sync(0xffffffffu, myCnt, o);
    if ((threadIdx.x & 31)==0 && myCnt) atomicAdd(&g_maskCnt[mIdx], myCnt);

    __syncthreads();
    for (int k=threadIdx.x; k<NBUCK; k+=1024){
        int c = sh[k];
        if (c) atomicAdd(&g_hist[mIdx][k], c);
    }

    /* ---- fused threshold: last block of this mask does the scan ---- */
    __threadfence();
    __syncthreads();
    __shared__ int isLast;
    if (threadIdx.x == 0) isLast = (atomicAdd(&g_bndDone[mIdx], 1) == 15) ? 1 : 0;
    __syncthreads();
    if (!isLast) return;

    __shared__ int arr[256];
    int t = threadIdx.x;
    int hloc[16];
    int hsum = 0;
    if (t < 256){
        int base = t*16;
#pragma unroll
        for (int j=0;j<16;j++){ hloc[j] = __ldcg(&g_hist[mIdx][base+j]); hsum += hloc[j]; }
        arr[t] = hsum;
    }
    __syncthreads();
#pragma unroll
    for (int o=1;o<256;o<<=1){
        int add = (t < 256 && t + o < 256) ? arr[t+o] : 0;
        __syncthreads();
        if (t < 256) arr[t] += add;
        __syncthreads();
    }
    int tot = arr[0];
    if (t == 0) g_bndTot[mIdx] = tot;
    if (tot <= KSUB) return;                  /* bStar stays -1, need 0 */
    if (t < 256){
        int cum = arr[t] - hsum;
#pragma unroll
        for (int j=15;j>=0;j--){
            int c2 = cum + hloc[j];
            if (cum < KSUB && c2 >= KSUB){
                g_bStar[mIdx] = t*16 + j;
                g_need[mIdx]  = KSUB - cum;
            }
            cum = c2;
        }
    }
}

/* ---------------- kernel 3: selection with WARP-AGGREGATED atomics ------
   Phase A counts sure/cand bits per thread; warp inclusive scan; ONE
   atomicAdd per warp per counter; phase B places at base+offset.
   Selection SETS identical to before (only g_pts order of sure picks
   permutes — chamfer is set-invariant).                                  */
__global__ void k_select(){
    int m = blockIdx.y;
    int wi = blockIdx.x*blockDim.x + threadIdx.x;
    unsigned bb = g_bnd[m][wi];
    int bs = g_bStar[m];
    int vbase = wi << 5;
    const unsigned* R = g_rand + vbase;

    int nS = 0, nC = 0;
    unsigned tmp = bb;
    while (tmp){
        int bit = __ffs(tmp)-1; tmp &= tmp-1;
        int bu = (int)(R[bit] >> 20);
        nS += (bu > bs);
        nC += (bu == bs);
    }

    int lane = threadIdx.x & 31;
    int incS = nS, incC = nC;
#pragma unroll
    for (int o=1;o<32;o<<=1){
        int a = __shfl_up_sync(0xffffffffu, incS, o);
        int c = __shfl_up_sync(0xffffffffu, incC, o);
        if (lane >= o){ incS += a; incC += c; }
    }
    int totS = __shfl_sync(0xffffffffu, incS, 31);
    int totC = __shfl_sync(0xffffffffu, incC, 31);
    int baseS = 0, baseC = 0;
    if (lane == 31){
        if (totS) baseS = atomicAdd(&g_sure[m],    totS);
        if (totC) baseC = atomicAdd(&g_candCnt[m], totC);
    }
    baseS = __shfl_sync(0xffffffffu, baseS, 31);
    baseC = __shfl_sync(0xffffffffu, baseC, 31);
    int offS = baseS + incS - nS;
    int offC = baseC + incC - nC;

    while (bb){
        int bit = __ffs(bb)-1; bb &= bb-1;
        unsigned rb = R[bit];
        int bu = (int)(rb >> 20);
        int v = vbase + bit;
        if (bu > bs){
            int dd = v/(HH*WW); int rr = v - dd*HH*WW; int hh = rr/WW; int ww = rr - hh*WW;
            g_pts[m][offS] = make_float4((float)dd,(float)hh,(float)ww,1.f);
            offS++;
        } else if (bu == bs){
            if (offC < CANDCAP){ g_candKey[m][offC] = rb >> 9; g_candIdx[m][offC] = v; }
            offC++;
        }
    }
}

/* ---------------- kernel 4: exact rank inside cut bucket ---------------- */
__global__ void k_fincand(){
    int m = blockIdx.x;
    int need = g_need[m];
    if (need <= 0) return;
    int n = min(g_candCnt[m], CANDCAP);
    int base = g_sure[m];
    for (int i=threadIdx.x; i<n; i+=blockDim.x){
        unsigned ki = g_candKey[m][i];
        int ii = g_candIdx[m][i];
        int rank = 0;
        for (int j=0;j<n;j++){
            unsigned kj = g_candKey[m][j];
            if (kj > ki || (kj == ki && g_candIdx[m][j] < ii)) rank++;
        }
        if (rank < need){
            int v = ii;
            int dd = v/(HH*WW); int rr = v - dd*HH*WW; int hh = rr/WW; int ww = rr - hh*WW;
            g_pts[m][base + rank] = make_float4((float)dd,(float)hh,(float)ww,1.f);
        }
    }
}

/* ---------------- kernel 5: chamfer (R11 scalar fmaf version) ----------- */
__global__ void k_cham(){
    int dir  = blockIdx.y;
    int pair = blockIdx.z;
    int mq = dir ? 8 + pair : pair;
    int mr = dir ? pair     : 8 + pair;

    __shared__ float4 sref[KSUB];
    for (int k=threadIdx.x; k<KSUB; k+=blockDim.x){
        float4 rr = g_pts[mr][k];
        if (rr.w > 0.5f) rr.w = rr.x*rr.x + rr.y*rr.y + rr.z*rr.z;
        else { rr.x=0.f; rr.y=0.f; rr.z=0.f; rr.w=1e30f; }
        sref[k] = rr;
    }
    __syncthreads();

    int qi = blockIdx.x*blockDim.x + threadIdx.x;
    float4 q = g_pts[mq][qi];
    float contrib = 0.f;
    if (q.w > 0.5f){
        float q2  = q.x*q.x + q.y*q.y + q.z*q.z;
        float qx2 = -2.f*q.x, qy2 = -2.f*q.y, qz2 = -2.f*q.z;
        float m0=3.4e38f, m1=3.4e38f, m2=3.4e38f, m3=3.4e38f;
        for (int j=0;j<KSUB;j+=4){
            float4 r0=sref[j], r1=sref[j+1], r2=sref[j+2], r3=sref[j+3];
            float t0 = fmaf(r0.x, qx2, fmaf(r0.y, qy2, fmaf(r0.z, qz2, r0.w)));
            float t1 = fmaf(r1.x, qx2, fmaf(r1.y, qy2, fmaf(r1.z, qz2, r1.w)));
            float t2 = fmaf(r2.x, qx2, fmaf(r2.y, qy2, fmaf(r2.z, qz2, r2.w)));
            float t3 = fmaf(r3.x, qx2, fmaf(r3.y, qy2, fmaf(r3.z, qz2, r3.w)));
            m0 = fminf(m0,t0); m1 = fminf(m1,t1);
            m2 = fminf(m2,t2); m3 = fminf(m3,t3);
        }
        float tmin = fminf(fminf(m0,m1), fminf(m2,m3));
        contrib = sqrtf(fmaxf(tmin + q2, 0.f));
    }
    __shared__ float sbuf[256];
    sbuf[threadIdx.x] = contrib;
    __syncthreads();
    for (int o=128;o;o>>=1){
        if (threadIdx.x < o) sbuf[threadIdx.x] += sbuf[threadIdx.x + o];
        __syncthreads();
    }
    if (threadIdx.x == 0) atomicAdd(&g_cham[dir][pair], (double)sbuf[0]);
}

/* ---------------- kernel 6: combine everything -------------------------- */
__global__ void k_final(float* out){
    const float SW[5]   = {1.f, 2.f, 1.5f, 2.5f, 1.5f};
    const float BASE[5] = {0.f, 2000.f, 8000.f, 1000.f, 3000.f};

    float dw[BB][CC];
    for (int b=0;b<BB;b++){
        float eff[CC], mx = 0.f;
        for (int c=0;c<CC;c++){
            float vv = (float)g_vols[b][c];
            float mult = fminf(sqrtf(BASE[c] / fmaxf(vv, 1e-5f)), 2.5f);
            eff[c] = SW[c]*mult;
            mx = fmaxf(mx, eff[c]);
        }
        for (int c=0;c<CC;c++) dw[b][c] = eff[c] / fmaxf(mx, 1e-5f);
    }

    double diceSum = 0.0, tvSum = 0.0;
    for (int b=0;b<BB;b++)
        for (int c=0;c<4;c++){
            double I = g_inter[b][c], P = g_psum[b][c], G = g_vols[b][c+1];
            diceSum += 1.0 - (2.0*I + 1e-5) / (P + G + 1e-5);
            double fp = P - I, fn = G - I;
            tvSum   += 1.0 - (I + 1e-5) / (I + 0.3*fp + 0.7*fn + 1e-5);
        }
    double ce = g_ce / ((double)BB * (double)VV);
    double dice_ce = 0.5*(diceSum/8.0) + 0.5*ce;

    double ssum = 0.0;
    for (int b=0;b<BB;b++){
        double cs = 0.0; int nval = 0;
        for (int c=0;c<4;c++){
            int pc = g_maskCnt[b*4 + c];
            int gc = g_maskCnt[8 + b*4 + c];
            bool p0 = (pc==0), g0 = (gc==0);
            if (p0 && g0) continue;
            nval++;
            double w = (double)dw[b][c+1];
            if (p0 != g0){ cs += w*10.0; }
            else {
                int pair = b*4 + c;
                int np = min(g_bndTot[pair],     KSUB); if (np < 1) np = 1;
                int nt = min(g_bndTot[8 + pair], KSUB); if (nt < 1) nt = 1;
                double mp = g_cham[0][pair] / (double)np;
                double mt = g_cham[1][pair] / (double)nt;
                cs += w * 0.5 * (mp + mt);
            }
        }
        ssum += (nval > 0) ? cs / (double)nval : 0.0;
    }
    double total = 0.4*dice_ce + 0.4*(tvSum/8.0) + 0.2*(ssum/(double)BB);
    out[0] = (float)total;
}

/* ---------------- launch ------------------------------------------------ */
extern "C" void kernel_launch(void* const* d_in, const int* in_sizes, int n_in,
                              void* d_out, int out_size){
    const float* pred = (const float*)d_in[0];
    const float* tgt  = (const float*)d_in[1];
    float* out = (float*)d_out;

    k_init<<<1024, 256>>>();
    k_main<<<dim3(KM_G, BB), 256>>>(pred, tgt);
    k_bnd<<<dim3(16, NMASK), 1024>>>();          /* fused threshold */
    dim3 gs(NW/256, NMASK);
    k_select<<<gs, 256>>>();                     /* 4th launch -> ncu window */
    k_fincand<<<NMASK, 256>>>();
    k_cham<<<dim3(KSUB/256, 2, NPAIR), 256>>>();
    k_final<<<1, 1>>>(out);
}